// round 14
// baseline (speedup 1.0000x reference)
#include <cuda_runtime.h>
#include <cuda_bf16.h>
#include <cstdint>
#include <stdint.h>
#include <math.h>

#define B 16
#define C1 18
#define C2 36
#define H 256
#define W 256
#define HW 65536
#define HIN 510
#define X2_ELEMS 37748736  // 16*36*256*256

// ---------------- scratch ----------------
__device__ float g_y1[B * C1 * HW];   // conv1 raw output

__device__ float g_c1_sum[C1], g_c1_sq[C1];
__device__ float g_se1_sum[B * C1];

__device__ float g_c2_sum[C2], g_c2_sq[C2];
__device__ float g_se2_sum[B * C2];

__device__ float g_rev_sum[B * C2];

// ---------------- helpers ----------------
__device__ __forceinline__ float warp_red(float v) {
#pragma unroll
    for (int o = 16; o > 0; o >>= 1) v += __shfl_down_sync(0xffffffffu, v, o);
    return v;
}
__device__ __forceinline__ float lrelu(float t) { return fmaxf(t, 0.1f * t); }

#define FMA2(acc, a, bb) asm("fma.rn.f32x2 %0, %1, %2, %0;" : "+l"(acc) : "l"(a), "l"(bb))
#define DUP2(d, v) asm("mov.b64 %0, {%1, %1};" : "=l"(d) : "r"(v))
#define PACK2(d, a, b) asm("mov.b64 %0, {%1, %2};" : "=l"(d) : "f"(a), "f"(b))
__device__ __forceinline__ float2 unpack2(unsigned long long v) {
    float2 r;
    asm("mov.b64 {%0, %1}, %2;" : "=f"(r.x), "=f"(r.y) : "l"(v));
    return r;
}

// bf16 mma (baseline PTX, sm_80+ — works on compute_103 target)
#define MMA16816(c, a0, a1, a2, a3, b0, b1) \
    asm volatile("mma.sync.aligned.m16n8k16.row.col.f32.bf16.bf16.f32 " \
        "{%0,%1,%2,%3}, {%4,%5,%6,%7}, {%8,%9}, {%0,%1,%2,%3};" \
        : "+f"((c)[0]), "+f"((c)[1]), "+f"((c)[2]), "+f"((c)[3]) \
        : "r"(a0), "r"(a1), "r"(a2), "r"(a3), "r"(b0), "r"(b1))

// round-to-nearest hi/lo bf16 split: v ~= hi + lo, residual ~2^-16 |v|
__device__ __forceinline__ void bf16_split(float v, __nv_bfloat16* hp, __nv_bfloat16* lp) {
    __nv_bfloat16 h = __float2bfloat16(v);
    *hp = h;
    *lp = __float2bfloat16(v - __bfloat162float(h));
}

// ---------------- K1: zero accumulated stats ----------------
__global__ void zero_stats() {
    int i = threadIdx.x;
    if (i < C1) { g_c1_sum[i] = 0.f; g_c1_sq[i] = 0.f; }
    if (i < C2) { g_c2_sum[i] = 0.f; g_c2_sq[i] = 0.f; }
    if (i < B * C2) { g_rev_sum[i] = 0.f; g_se2_sum[i] = 0.f; }
    if (i < B * C1) g_se1_sum[i] = 0.f;
}

// ---- K2: conv1 4x4 s2 p2 (3->18) -> g_y1, fused bn1 stats, FFMA2 -------
__global__ __launch_bounds__(256) void conv1_kernel(
    const float* __restrict__ x, const float* __restrict__ wt,
    const float* __restrict__ bias) {
    __shared__ float s_in[3][4][516];
    __shared__ __align__(16) float s_wp[9 * 3 * 16 * 2];
    __shared__ float s_red[8][36];
    const int oh = blockIdx.x, b = blockIdx.y, tid = threadIdx.x;

    for (int i = tid; i < 864; i += 256) {
        int k = i & 15; int t = i >> 4; int ci = t % 3; int co = t / 3;
        s_wp[(((co >> 1) * 3 + ci) * 16 + k) * 2 + (co & 1)] = wt[i];
    }
#pragma unroll
    for (int ci = 0; ci < 3; ci++) {
#pragma unroll
        for (int kh = 0; kh < 4; kh++) {
            int row = 2 * oh - 2 + kh;
            const float* src = &x[((size_t)(b * 3 + ci) * HIN + row) * HIN];
            bool rowok = (unsigned)row < HIN;
            for (int cc = tid; cc < 514; cc += 256) {
                int col = cc - 2;
                float v = (rowok && (unsigned)col < HIN) ? src[col] : 0.f;
                s_in[ci][kh][cc] = v;
            }
        }
    }
    __syncthreads();

    const int ow = tid;
    unsigned long long acc2[9];
#pragma unroll
    for (int p = 0; p < 9; p++) {
        float2 bb = *(const float2*)(bias + 2 * p);
        PACK2(acc2[p], bb.x, bb.y);
    }

#pragma unroll
    for (int ci = 0; ci < 3; ci++) {
        float xv[16];
#pragma unroll
        for (int kh = 0; kh < 4; kh++) {
            float2 p0 = *(const float2*)&s_in[ci][kh][2 * ow];
            float2 p1 = *(const float2*)&s_in[ci][kh][2 * ow + 2];
            xv[kh * 4 + 0] = p0.x; xv[kh * 4 + 1] = p0.y;
            xv[kh * 4 + 2] = p1.x; xv[kh * 4 + 3] = p1.y;
        }
        unsigned long long xs[16];
#pragma unroll
        for (int k = 0; k < 16; k++) { DUP2(xs[k], __float_as_uint(xv[k])); }
#pragma unroll
        for (int p = 0; p < 9; p++) {
            const ulonglong2* wp = (const ulonglong2*)&s_wp[((p * 3 + ci) * 16) * 2];
#pragma unroll
            for (int j = 0; j < 8; j++) {
                ulonglong2 u = wp[j];
                FMA2(acc2[p], xs[2 * j], u.x);
                FMA2(acc2[p], xs[2 * j + 1], u.y);
            }
        }
    }

    const int lane = tid & 31, wid = tid >> 5;
#pragma unroll
    for (int p = 0; p < 9; p++) {
        float2 u = unpack2(acc2[p]);
#pragma unroll
        for (int h = 0; h < 2; h++) {
            const int co = 2 * p + h;
            float val = (h == 0) ? u.x : u.y;
            g_y1[((size_t)(b * C1 + co) * H + oh) * W + ow] = val;
            float s = warp_red(val);
            float q = warp_red(val * val);
            if (lane == 0) { s_red[wid][co] = s; s_red[wid][18 + co] = q; }
        }
    }
    __syncthreads();
    if (tid < 36) {
        float v = 0.f;
#pragma unroll
        for (int w = 0; w < 8; w++) v += s_red[w][tid];
        if (tid < 18) atomicAdd(&g_c1_sum[tid], v);
        else          atomicAdd(&g_c1_sq[tid - 18], v);
    }
}

// ---- K3: review + se1 sums, read-only over y1, smem accumulators --------
__global__ __launch_bounds__(256) void bn1_review_kernel(
    const float* __restrict__ bn1g, const float* __restrict__ bn1b,
    const float* __restrict__ rw, const float* __restrict__ rb) {
    __shared__ __align__(16) float s_w2[36 * 18 * 2];
    __shared__ __align__(16) float s_b2[36 * 2];
    __shared__ float s_scale[18], s_shift[18];
    __shared__ float s_rev[8][36];
    __shared__ float s_se[8][18];
    const int b = blockIdx.x, chunk = blockIdx.y, tid = threadIdx.x;
    const int lane = tid & 31, wid = tid >> 5;

    if (tid < 18) {
        const float inv = 1.f / 1048576.f;
        float m = g_c1_sum[tid] * inv;
        float var = g_c1_sq[tid] * inv - m * m;
        float sc = bn1g[tid] * rsqrtf(var + 1e-5f);
        s_scale[tid] = sc;
        s_shift[tid] = bn1b[tid] - m * sc;
    }
    for (int i = tid; i < 1296; i += 256) s_w2[i] = rw[i >> 1];
    if (tid < 72) s_b2[tid] = rb[tid >> 1];
    for (int i = tid; i < 8 * 36; i += 256) ((float*)s_rev)[i] = 0.f;
    for (int i = tid; i < 8 * 18; i += 256) ((float*)s_se)[i] = 0.f;
    __syncthreads();

#pragma unroll 1
    for (int batch = 0; batch < 2; batch++) {
        const int px = chunk * 1024 + batch * 512 + tid * 2;
        unsigned long long x2[18];
#pragma unroll
        for (int c = 0; c < 18; c++) {
            float2 v = *(const float2*)&g_y1[(size_t)(b * C1 + c) * HW + px];
            float sc = s_scale[c], sh = s_shift[c];
            float a0 = lrelu(v.x * sc + sh);
            float a1 = lrelu(v.y * sc + sh);
            PACK2(x2[c], a0, a1);
            float r = warp_red(a0 + a1);
            if (lane == 0) s_se[wid][c] += r;
        }
#pragma unroll 2
        for (int o = 0; o < 36; o++) {
            unsigned long long acc = *(const unsigned long long*)&s_b2[o * 2];
            const ulonglong2* wp = (const ulonglong2*)&s_w2[o * 36];
#pragma unroll
            for (int j = 0; j < 9; j++) {
                ulonglong2 u = wp[j];
                FMA2(acc, x2[2 * j], u.x);
                FMA2(acc, x2[2 * j + 1], u.y);
            }
            float2 rr = unpack2(acc);
            float r = warp_red(fmaxf(rr.x, 0.f) + fmaxf(rr.y, 0.f));
            if (lane == 0) s_rev[wid][o] += r;
        }
    }
    __syncthreads();
    if (tid < 36) {
        float v = 0.f;
#pragma unroll
        for (int w = 0; w < 8; w++) v += s_rev[w][tid];
        atomicAdd(&g_rev_sum[b * C2 + tid], v);
    }
    if (tid >= 64 && tid < 82) {
        const int c = tid - 64;
        float v = 0.f;
#pragma unroll
        for (int w = 0; w < 8; w++) v += s_se[w][c];
        atomicAdd(&g_se1_sum[b * C1 + c], v);
    }
}

// ---- K4 (PROFILED SLOT): conv2 via mma.sync bf16x3 implicit GEMM --------
// Per CTA (128 thr, 4 warps): 64-px tile of one row. D[64,40] = A[64,176]*B^T.
// Warp w owns px [w*16, w*16+16); 5 n-tiles of 8 co (co 36..39 zero-padded).
#define KPAD 176
#define KREAL 162
#define ASTR 186          // bf16 elems per row (93 words, odd -> few conflicts)
#define AH_OFF 0          // 64*186*2 = 23808
#define AL_OFF 23808
#define WH_OFF 47616      // 40*186*2 = 14880
#define WL_OFF 62496
#define SC_OFF 77376
#define SH_OFF 77448
#define S1_OFF 77520
#define TMP_OFF 77592
#define MMA_SMEM 77664

__global__ __launch_bounds__(128, 2) void conv2_mma(
    const float* __restrict__ wt, const float* __restrict__ bias,
    const float* __restrict__ bn1g, const float* __restrict__ bn1b,
    const float* __restrict__ se1w1, const float* __restrict__ se1w2,
    float* __restrict__ out) {
    extern __shared__ char sm[];
    __nv_bfloat16* Ah = (__nv_bfloat16*)(sm + AH_OFF);
    __nv_bfloat16* Al = (__nv_bfloat16*)(sm + AL_OFF);
    __nv_bfloat16* Wh = (__nv_bfloat16*)(sm + WH_OFF);
    __nv_bfloat16* Wl = (__nv_bfloat16*)(sm + WL_OFF);
    float* s_scale = (float*)(sm + SC_OFF);
    float* s_shift = (float*)(sm + SH_OFF);
    float* s_s1    = (float*)(sm + S1_OFF);
    float* s_tmp   = (float*)(sm + TMP_OFF);
    const int tid = threadIdx.x, wid = tid >> 5, lane = tid & 31;
    const int b = blockIdx.z, oh = blockIdx.y, ow0 = blockIdx.x * 64;

    // bn1 params + SE1 MLP
    if (tid < 18) {
        const float inv = 1.f / 1048576.f;
        float m = g_c1_sum[tid] * inv;
        float var = g_c1_sq[tid] * inv - m * m;
        float sc = bn1g[tid] * rsqrtf(var + 1e-5f);
        s_scale[tid] = sc;
        s_shift[tid] = bn1b[tid] - m * sc;
        s_tmp[tid] = g_se1_sum[b * C1 + tid] * (1.f / 65536.f) * se1w1[tid];
    }
    __syncthreads();
    if (tid < 18) {
        float h = 0.f;
#pragma unroll
        for (int c = 0; c < 18; c++) h += s_tmp[c];
        h = fmaxf(h, 0.f);
        s_s1[tid] = 1.f / (1.f + expf(-h * se1w2[tid]));
    }
    __syncthreads();

    // stage W [40 co x 176 k], SE1 folded; rows/cols beyond real extent = 0
    for (int i = tid; i < 40 * KPAD; i += 128) {
        int co = i / KPAD, k = i - co * KPAD;
        float w = 0.f;
        if (co < 36 && k < KREAL) {
            int ci = k / 9, tap = k - ci * 9;
            w = wt[(co * 18 + ci) * 9 + tap] * s_s1[ci];
        }
        bf16_split(w, &Wh[co * ASTR + k], &Wl[co * ASTR + k]);
    }
    // stage A im2col [64 px x 176 k], bn1+leaky applied; px fastest (coalesced)
    for (int i = tid; i < 64 * KPAD; i += 128) {
        int k = i >> 6, px = i & 63;
        float v = 0.f;
        if (k < KREAL) {
            int ci = k / 9, tap = k - ci * 9;
            int dy = tap / 3, dx = tap - dy * 3;
            int r = oh - 1 + dy, c = ow0 + px + dx - 1;
            if ((unsigned)r < H && (unsigned)c < W)
                v = lrelu(g_y1[((size_t)(b * C1 + ci) * H + r) * W + c] * s_scale[ci] + s_shift[ci]);
        }
        bf16_split(v, &Ah[px * ASTR + k], &Al[px * ASTR + k]);
    }
    __syncthreads();

    // mma mainloop
    float acc[5][4];
#pragma unroll
    for (int nt = 0; nt < 5; nt++)
#pragma unroll
        for (int j = 0; j < 4; j++) acc[nt][j] = 0.f;

    const int g = lane >> 2, tg = lane & 3;
    const int pxb = wid * 16;

#pragma unroll 1
    for (int ks = 0; ks < 11; ks++) {
        const int k0 = ks * 16 + tg * 2;
        const int r0 = (pxb + g) * ASTR, r1 = (pxb + g + 8) * ASTR;
        uint32_t ah0 = *(const uint32_t*)&Ah[r0 + k0];
        uint32_t ah1 = *(const uint32_t*)&Ah[r1 + k0];
        uint32_t ah2 = *(const uint32_t*)&Ah[r0 + k0 + 8];
        uint32_t ah3 = *(const uint32_t*)&Ah[r1 + k0 + 8];
        uint32_t al0 = *(const uint32_t*)&Al[r0 + k0];
        uint32_t al1 = *(const uint32_t*)&Al[r1 + k0];
        uint32_t al2 = *(const uint32_t*)&Al[r0 + k0 + 8];
        uint32_t al3 = *(const uint32_t*)&Al[r1 + k0 + 8];
#pragma unroll
        for (int nt = 0; nt < 5; nt++) {
            const int wrow = (nt * 8 + g) * ASTR + k0;
            uint32_t bh0 = *(const uint32_t*)&Wh[wrow];
            uint32_t bh1 = *(const uint32_t*)&Wh[wrow + 8];
            uint32_t bl0 = *(const uint32_t*)&Wl[wrow];
            uint32_t bl1 = *(const uint32_t*)&Wl[wrow + 8];
            MMA16816(acc[nt], ah0, ah1, ah2, ah3, bh0, bh1);
            MMA16816(acc[nt], ah0, ah1, ah2, ah3, bl0, bl1);
            MMA16816(acc[nt], al0, al1, al2, al3, bh0, bh1);
        }
    }

    // epilogue: transpose D through smem (reuse Ah region), then coalesced
    // stores + fused bias + bn2 stats
    __syncthreads();
    float* D = (float*)(sm + AH_OFF);   // [40 co][65 px-stride]
#pragma unroll
    for (int nt = 0; nt < 5; nt++) {
        int co0 = nt * 8 + 2 * tg;
        int p0 = pxb + g;
        D[co0 * 65 + p0] = acc[nt][0];
        D[(co0 + 1) * 65 + p0] = acc[nt][1];
        D[co0 * 65 + p0 + 8] = acc[nt][2];
        D[(co0 + 1) * 65 + p0 + 8] = acc[nt][3];
    }
    __syncthreads();
    for (int co = wid; co < 36; co += 4) {
        float bb = bias[co];
        float v0 = D[co * 65 + lane] + bb;
        float v1 = D[co * 65 + 32 + lane] + bb;
        size_t o = ((size_t)(b * C2 + co) * H + oh) * W + ow0;
        out[o + lane] = v0;
        out[o + 32 + lane] = v1;
        float ts = warp_red(v0 + v1);
        float tq = warp_red(v0 * v0 + v1 * v1);
        if (lane == 0) { atomicAdd(&g_c2_sum[co], ts); atomicAdd(&g_c2_sq[co], tq); }
    }
}

// ---- K5: se2 pooling sums, inline bn2 finalize (reads d_out = raw y2) ---
__global__ __launch_bounds__(256) void stats2_kernel(
    const float* __restrict__ out,
    const float* __restrict__ bn2g, const float* __restrict__ bn2b) {
    __shared__ float sm[8];
    const int bc = blockIdx.x, part = blockIdx.y, tid = threadIdx.x, c = bc % C2;
    const float inv = 1.f / 1048576.f;
    const float m = g_c2_sum[c] * inv;
    const float var = g_c2_sq[c] * inv - m * m;
    const float sc = bn2g[c] * rsqrtf(var + 1e-5f);
    const float sh = bn2b[c] - m * sc;
    const float4* p = (const float4*)(out + (size_t)bc * HW + (size_t)part * 16384);
    float s = 0.f;
    for (int i = tid; i < 4096; i += 256) {
        float4 v = p[i];
        s += lrelu(v.x * sc + sh) + lrelu(v.y * sc + sh)
           + lrelu(v.z * sc + sh) + lrelu(v.w * sc + sh);
    }
    int lane = tid & 31, wid = tid >> 5;
    s = warp_red(s);
    if (lane == 0) sm[wid] = s;
    __syncthreads();
    if (wid == 0) {
        s = (lane < 8) ? sm[lane] : 0.f;
        s = warp_red(s);
        if (lane == 0) atomicAdd(&g_se2_sum[bc], s);
    }
}

// ---- K6: out = lrelu(bn2(out)) * s2 in place, inline bn2 + se2 MLP ------
__global__ __launch_bounds__(256) void finalize_x2_kernel(
    float* __restrict__ out,
    const float* __restrict__ bn2g, const float* __restrict__ bn2b,
    const float* __restrict__ se2w1, const float* __restrict__ se2w2) {
    __shared__ float sh_hh[2];
    const int bc = blockIdx.x, part = blockIdx.y, tid = threadIdx.x;
    const int b = bc / C2, c = bc % C2;
    const float inv = 1.f / 1048576.f;
    const float m = g_c2_sum[c] * inv;
    const float var = g_c2_sq[c] * inv - m * m;
    const float sc = bn2g[c] * rsqrtf(var + 1e-5f);
    const float sh = bn2b[c] - m * sc;
    if (tid < 2) {
        float a = 0.f;
        for (int cc = 0; cc < C2; cc++)
            a += g_se2_sum[b * C2 + cc] * (1.f / 65536.f) * se2w1[tid * C2 + cc];
        sh_hh[tid] = fmaxf(a, 0.f);
    }
    __syncthreads();
    const float s2 = 1.f / (1.f + expf(-(sh_hh[0] * se2w2[c * 2] + sh_hh[1] * se2w2[c * 2 + 1])));
    float4* p = (float4*)(out + (size_t)bc * HW + (size_t)part * 16384);
    for (int i = tid; i < 4096; i += 256) {
        float4 v = p[i];
        v.x = lrelu(v.x * sc + sh) * s2;
        v.y = lrelu(v.y * sc + sh) * s2;
        v.z = lrelu(v.z * sc + sh) * s2;
        v.w = lrelu(v.w * sc + sh) * s2;
        p[i] = v;
    }
}

// ---- K7: head; inline se2 MLP (Haar dwt/idwt collapses to identity) -----
__global__ void final_kernel(const float* __restrict__ fw, const float* __restrict__ fb,
                             const float* __restrict__ se2w1, const float* __restrict__ se2w2,
                             float* __restrict__ out) {
    const int t = threadIdx.x;
    if (t < 32) {
        const int b = t >> 1, k = t & 1;
        const float inv = 1.f / 65536.f;
        float hh0 = 0.f, hh1 = 0.f;
        for (int cc = 0; cc < C2; cc++) {
            float mm = g_se2_sum[b * C2 + cc] * inv;
            hh0 += mm * se2w1[cc];
            hh1 += mm * se2w1[C2 + cc];
        }
        hh0 = fmaxf(hh0, 0.f); hh1 = fmaxf(hh1, 0.f);
        float a = fb[k];
        for (int o = 0; o < C2; o++) {
            float s2 = 1.f / (1.f + expf(-(hh0 * se2w2[o * 2] + hh1 * se2w2[o * 2 + 1])));
            float pool = s2 * g_se2_sum[b * C2 + o] * inv + g_rev_sum[b * C2 + o] * inv;
            a += pool * fw[k * C2 + o];
        }
        out[X2_ELEMS + t] = a;
    }
}

// ---------------- launch ----------------
extern "C" void kernel_launch(void* const* d_in, const int* in_sizes, int n_in,
                              void* d_out, int out_size) {
    const float* x     = (const float*)d_in[0];
    const float* c1w   = (const float*)d_in[1];
    const float* c1b   = (const float*)d_in[2];
    const float* bn1g  = (const float*)d_in[3];
    const float* bn1b  = (const float*)d_in[4];
    const float* se1w1 = (const float*)d_in[5];
    const float* se1w2 = (const float*)d_in[6];
    const float* c2w   = (const float*)d_in[7];
    const float* c2b   = (const float*)d_in[8];
    const float* bn2g  = (const float*)d_in[9];
    const float* bn2b  = (const float*)d_in[10];
    const float* se2w1 = (const float*)d_in[11];
    const float* se2w2 = (const float*)d_in[12];
    const float* rw    = (const float*)d_in[13];
    const float* rb    = (const float*)d_in[14];
    const float* fw    = (const float*)d_in[15];
    const float* fb    = (const float*)d_in[16];
    float* out = (float*)d_out;

    cudaFuncSetAttribute(conv2_mma, cudaFuncAttributeMaxDynamicSharedMemorySize, MMA_SMEM);

    zero_stats<<<1, 576>>>();                                      // 1
    conv1_kernel<<<dim3(256, 16), 256>>>(x, c1w, c1b);             // 2
    bn1_review_kernel<<<dim3(16, 64), 256>>>(bn1g, bn1b, rw, rb);  // 3
    conv2_mma<<<dim3(4, 256, 16), 128, MMA_SMEM>>>(c2w, c2b, bn1g, bn1b, se1w1, se1w2, out); // 4 <- profiled
    stats2_kernel<<<dim3(576, 4), 256>>>(out, bn2g, bn2b);         // 5
    finalize_x2_kernel<<<dim3(576, 4), 256>>>(out, bn2g, bn2b, se2w1, se2w2); // 6
    final_kernel<<<1, 32>>>(fw, fb, se2w1, se2w2, out);            // 7
}

// round 15
// speedup vs baseline: 3.8578x; 3.8578x over previous
#include <cuda_runtime.h>
#include <cuda_bf16.h>
#include <cstdint>
#include <stdint.h>
#include <math.h>

#define B 16
#define C1 18
#define C2 36
#define H 256
#define W 256
#define HW 65536
#define HIN 510
#define X2_ELEMS 37748736  // 16*36*256*256

// ---------------- scratch ----------------
__device__ float g_y1[B * C1 * HW];   // conv1 raw output
__device__ __align__(16) __nv_bfloat16 g_wh[9 * 40 * 18];  // [tap][co40][ci18]
__device__ __align__(16) __nv_bfloat16 g_wl[9 * 40 * 18];

__device__ float g_c1_sum[C1], g_c1_sq[C1];
__device__ float g_se1_sum[B * C1];

__device__ float g_c2_sum[C2], g_c2_sq[C2];
__device__ float g_se2_sum[B * C2];

__device__ float g_rev_sum[B * C2];

// ---------------- helpers ----------------
__device__ __forceinline__ float warp_red(float v) {
#pragma unroll
    for (int o = 16; o > 0; o >>= 1) v += __shfl_down_sync(0xffffffffu, v, o);
    return v;
}
__device__ __forceinline__ float lrelu(float t) { return fmaxf(t, 0.1f * t); }

#define FMA2(acc, a, bb) asm("fma.rn.f32x2 %0, %1, %2, %0;" : "+l"(acc) : "l"(a), "l"(bb))
#define DUP2(d, v) asm("mov.b64 %0, {%1, %1};" : "=l"(d) : "r"(v))
#define PACK2(d, a, b) asm("mov.b64 %0, {%1, %2};" : "=l"(d) : "f"(a), "f"(b))
__device__ __forceinline__ float2 unpack2(unsigned long long v) {
    float2 r;
    asm("mov.b64 {%0, %1}, %2;" : "=f"(r.x), "=f"(r.y) : "l"(v));
    return r;
}

#define MMA16816(c, a0, a1, a2, a3, b0, b1) \
    asm volatile("mma.sync.aligned.m16n8k16.row.col.f32.bf16.bf16.f32 " \
        "{%0,%1,%2,%3}, {%4,%5,%6,%7}, {%8,%9}, {%0,%1,%2,%3};" \
        : "+f"((c)[0]), "+f"((c)[1]), "+f"((c)[2]), "+f"((c)[3]) \
        : "r"(a0), "r"(a1), "r"(a2), "r"(a3), "r"(b0), "r"(b1))

__device__ __forceinline__ void bf16_split(float v, __nv_bfloat16* hp, __nv_bfloat16* lp) {
    __nv_bfloat16 h = __float2bfloat16(v);
    *hp = h;
    *lp = __float2bfloat16(v - __bfloat162float(h));
}

// ---------------- K1: zero stats + precompute split weights -------------
__global__ void zero_stats(const float* __restrict__ c2w) {
    int i = threadIdx.x;
    if (i < C1) { g_c1_sum[i] = 0.f; g_c1_sq[i] = 0.f; }
    if (i < C2) { g_c2_sum[i] = 0.f; g_c2_sq[i] = 0.f; }
    if (i < B * C2) { g_rev_sum[i] = 0.f; g_se2_sum[i] = 0.f; }
    if (i < B * C1) g_se1_sum[i] = 0.f;
    for (int j = i; j < 9 * 40 * 18; j += 576) {
        int tap = j / 720; int r = j % 720; int co = r / 18; int ci = r % 18;
        float w = (co < 36) ? c2w[(co * 18 + ci) * 9 + tap] : 0.f;
        bf16_split(w, &g_wh[j], &g_wl[j]);
    }
}

// ---- K2: conv1 4x4 s2 p2 (3->18) -> g_y1, fused bn1 stats, FFMA2 -------
__global__ __launch_bounds__(256) void conv1_kernel(
    const float* __restrict__ x, const float* __restrict__ wt,
    const float* __restrict__ bias) {
    __shared__ float s_in[3][4][516];
    __shared__ __align__(16) float s_wp[9 * 3 * 16 * 2];
    __shared__ float s_red[8][36];
    const int oh = blockIdx.x, b = blockIdx.y, tid = threadIdx.x;

    for (int i = tid; i < 864; i += 256) {
        int k = i & 15; int t = i >> 4; int ci = t % 3; int co = t / 3;
        s_wp[(((co >> 1) * 3 + ci) * 16 + k) * 2 + (co & 1)] = wt[i];
    }
#pragma unroll
    for (int ci = 0; ci < 3; ci++) {
#pragma unroll
        for (int kh = 0; kh < 4; kh++) {
            int row = 2 * oh - 2 + kh;
            const float* src = &x[((size_t)(b * 3 + ci) * HIN + row) * HIN];
            bool rowok = (unsigned)row < HIN;
            for (int cc = tid; cc < 514; cc += 256) {
                int col = cc - 2;
                float v = (rowok && (unsigned)col < HIN) ? src[col] : 0.f;
                s_in[ci][kh][cc] = v;
            }
        }
    }
    __syncthreads();

    const int ow = tid;
    unsigned long long acc2[9];
#pragma unroll
    for (int p = 0; p < 9; p++) {
        float2 bb = *(const float2*)(bias + 2 * p);
        PACK2(acc2[p], bb.x, bb.y);
    }

#pragma unroll
    for (int ci = 0; ci < 3; ci++) {
        float xv[16];
#pragma unroll
        for (int kh = 0; kh < 4; kh++) {
            float2 p0 = *(const float2*)&s_in[ci][kh][2 * ow];
            float2 p1 = *(const float2*)&s_in[ci][kh][2 * ow + 2];
            xv[kh * 4 + 0] = p0.x; xv[kh * 4 + 1] = p0.y;
            xv[kh * 4 + 2] = p1.x; xv[kh * 4 + 3] = p1.y;
        }
        unsigned long long xs[16];
#pragma unroll
        for (int k = 0; k < 16; k++) { DUP2(xs[k], __float_as_uint(xv[k])); }
#pragma unroll
        for (int p = 0; p < 9; p++) {
            const ulonglong2* wp = (const ulonglong2*)&s_wp[((p * 3 + ci) * 16) * 2];
#pragma unroll
            for (int j = 0; j < 8; j++) {
                ulonglong2 u = wp[j];
                FMA2(acc2[p], xs[2 * j], u.x);
                FMA2(acc2[p], xs[2 * j + 1], u.y);
            }
        }
    }

    const int lane = tid & 31, wid = tid >> 5;
#pragma unroll
    for (int p = 0; p < 9; p++) {
        float2 u = unpack2(acc2[p]);
#pragma unroll
        for (int h = 0; h < 2; h++) {
            const int co = 2 * p + h;
            float val = (h == 0) ? u.x : u.y;
            g_y1[((size_t)(b * C1 + co) * H + oh) * W + ow] = val;
            float s = warp_red(val);
            float q = warp_red(val * val);
            if (lane == 0) { s_red[wid][co] = s; s_red[wid][18 + co] = q; }
        }
    }
    __syncthreads();
    if (tid < 36) {
        float v = 0.f;
#pragma unroll
        for (int w = 0; w < 8; w++) v += s_red[w][tid];
        if (tid < 18) atomicAdd(&g_c1_sum[tid], v);
        else          atomicAdd(&g_c1_sq[tid - 18], v);
    }
}

// ---- K3: review + se1 sums, read-only over y1, smem accumulators --------
__global__ __launch_bounds__(256) void bn1_review_kernel(
    const float* __restrict__ bn1g, const float* __restrict__ bn1b,
    const float* __restrict__ rw, const float* __restrict__ rb) {
    __shared__ __align__(16) float s_w2[36 * 18 * 2];
    __shared__ __align__(16) float s_b2[36 * 2];
    __shared__ float s_scale[18], s_shift[18];
    __shared__ float s_rev[8][36];
    __shared__ float s_se[8][18];
    const int b = blockIdx.x, chunk = blockIdx.y, tid = threadIdx.x;
    const int lane = tid & 31, wid = tid >> 5;

    if (tid < 18) {
        const float inv = 1.f / 1048576.f;
        float m = g_c1_sum[tid] * inv;
        float var = g_c1_sq[tid] * inv - m * m;
        float sc = bn1g[tid] * rsqrtf(var + 1e-5f);
        s_scale[tid] = sc;
        s_shift[tid] = bn1b[tid] - m * sc;
    }
    for (int i = tid; i < 1296; i += 256) s_w2[i] = rw[i >> 1];
    if (tid < 72) s_b2[tid] = rb[tid >> 1];
    for (int i = tid; i < 8 * 36; i += 256) ((float*)s_rev)[i] = 0.f;
    for (int i = tid; i < 8 * 18; i += 256) ((float*)s_se)[i] = 0.f;
    __syncthreads();

#pragma unroll 1
    for (int batch = 0; batch < 2; batch++) {
        const int px = chunk * 1024 + batch * 512 + tid * 2;
        unsigned long long x2[18];
#pragma unroll
        for (int c = 0; c < 18; c++) {
            float2 v = *(const float2*)&g_y1[(size_t)(b * C1 + c) * HW + px];
            float sc = s_scale[c], sh = s_shift[c];
            float a0 = lrelu(v.x * sc + sh);
            float a1 = lrelu(v.y * sc + sh);
            PACK2(x2[c], a0, a1);
            float r = warp_red(a0 + a1);
            if (lane == 0) s_se[wid][c] += r;
        }
#pragma unroll 2
        for (int o = 0; o < 36; o++) {
            unsigned long long acc = *(const unsigned long long*)&s_b2[o * 2];
            const ulonglong2* wp = (const ulonglong2*)&s_w2[o * 36];
#pragma unroll
            for (int j = 0; j < 9; j++) {
                ulonglong2 u = wp[j];
                FMA2(acc, x2[2 * j], u.x);
                FMA2(acc, x2[2 * j + 1], u.y);
            }
            float2 rr = unpack2(acc);
            float r = warp_red(fmaxf(rr.x, 0.f) + fmaxf(rr.y, 0.f));
            if (lane == 0) s_rev[wid][o] += r;
        }
    }
    __syncthreads();
    if (tid < 36) {
        float v = 0.f;
#pragma unroll
        for (int w = 0; w < 8; w++) v += s_rev[w][tid];
        atomicAdd(&g_rev_sum[b * C2 + tid], v);
    }
    if (tid >= 64 && tid < 82) {
        const int c = tid - 64;
        float v = 0.f;
#pragma unroll
        for (int w = 0; w < 8; w++) v += s_se[w][c];
        atomicAdd(&g_se1_sum[b * C1 + c], v);
    }
}

// ---- K4 (PROFILED SLOT): conv2 as 9 shifted GEMMs via mma.sync bf16x3 ---
// CTA: 256 thr (8 warps x 16 px) on a 128-px row tile.
// A[3 rows][130 px][18 ci] staged once (raw, bn1+SE1 folded, hi/lo split);
// tap (dy,dx) = smem offset. W split precomputed globally, copied as uint4.
#define AROW 2340          // 130*18 elems per dy row
#define AH_OFF 0           // 3*130*18*2 = 14040 B
#define AL_OFF 14040
#define WH_OFF 28080       // 6480*2 = 12960 B
#define WL_OFF 41040
#define SC2_OFF 54000
#define SH2_OFF 54072
#define S1_OFF  54144
#define TMP_OFF 54216
#define MMA_SMEM 54288

__global__ __launch_bounds__(256, 4) void conv2_mma(
    const float* __restrict__ bias,
    const float* __restrict__ bn1g, const float* __restrict__ bn1b,
    const float* __restrict__ se1w1, const float* __restrict__ se1w2,
    float* __restrict__ out) {
    extern __shared__ char sm[];
    __nv_bfloat16* Ah = (__nv_bfloat16*)(sm + AH_OFF);
    __nv_bfloat16* Al = (__nv_bfloat16*)(sm + AL_OFF);
    __nv_bfloat16* Wh = (__nv_bfloat16*)(sm + WH_OFF);
    __nv_bfloat16* Wl = (__nv_bfloat16*)(sm + WL_OFF);
    float* s_scale2 = (float*)(sm + SC2_OFF);
    float* s_shift2 = (float*)(sm + SH2_OFF);
    float* s_s1     = (float*)(sm + S1_OFF);
    float* s_tmp    = (float*)(sm + TMP_OFF);
    const int tid = threadIdx.x, wid = tid >> 5, lane = tid & 31;
    const int b = blockIdx.z, oh = blockIdx.y, ow0 = blockIdx.x * 128;

    // bn1 params + SE1 MLP; fold s1 into A's affine (s1 > 0 commutes w/ lrelu)
    if (tid < 18)
        s_tmp[tid] = g_se1_sum[b * C1 + tid] * (1.f / 65536.f) * se1w1[tid];
    __syncthreads();
    if (tid < 18) {
        float h = 0.f;
#pragma unroll
        for (int c = 0; c < 18; c++) h += s_tmp[c];
        h = fmaxf(h, 0.f);
        float s1 = 1.f / (1.f + expf(-h * se1w2[tid]));
        const float inv = 1.f / 1048576.f;
        float m = g_c1_sum[tid] * inv;
        float var = g_c1_sq[tid] * inv - m * m;
        float sc = bn1g[tid] * rsqrtf(var + 1e-5f);
        s_scale2[tid] = sc * s1;
        s_shift2[tid] = (bn1b[tid] - m * sc) * s1;
    }
    // copy W splits (uint4: 810 each)
    {
        const uint4* sh = (const uint4*)g_wh;
        const uint4* sl = (const uint4*)g_wl;
        uint4* dh = (uint4*)Wh;
        uint4* dl = (uint4*)Wl;
        for (int i = tid; i < 810; i += 256) { dh[i] = sh[i]; dl[i] = sl[i]; }
    }
    __syncthreads();

    // stage A: [ci][dyr][px] iteration for coalesced LDG; store [dyr][px][ci]
    for (int i = tid; i < 18 * 3 * 130; i += 256) {
        int ci = i / 390; int r = i % 390; int dyr = r / 130; int px = r % 130;
        int grow = oh - 1 + dyr, gcol = ow0 - 1 + px;
        float v = 0.f;
        if ((unsigned)grow < H && (unsigned)gcol < W)
            v = lrelu(g_y1[((size_t)(b * C1 + ci) * H + grow) * W + gcol]
                      * s_scale2[ci] + s_shift2[ci]);
        int o = dyr * AROW + px * 18 + ci;
        bf16_split(v, &Ah[o], &Al[o]);
    }
    __syncthreads();

    float acc[5][4];
#pragma unroll
    for (int nt = 0; nt < 5; nt++)
#pragma unroll
        for (int j = 0; j < 4; j++) acc[nt][j] = 0.f;

    const int g = lane >> 2, tg = lane & 3;
    const int pxb = wid * 16;

#pragma unroll
    for (int tap = 0; tap < 9; tap++) {
        const int dy = tap / 3, dx = tap % 3;
        const int base0 = dy * AROW + (pxb + g + dx) * 18;
        const int base1 = base0 + 8 * 18;
        // kstep 0: k = tg*2 (+8)
        const int k0 = tg * 2;
        uint32_t ah0 = *(const uint32_t*)&Ah[base0 + k0];
        uint32_t ah1 = *(const uint32_t*)&Ah[base1 + k0];
        uint32_t ah2 = *(const uint32_t*)&Ah[base0 + k0 + 8];
        uint32_t ah3 = *(const uint32_t*)&Ah[base1 + k0 + 8];
        uint32_t al0 = *(const uint32_t*)&Al[base0 + k0];
        uint32_t al1 = *(const uint32_t*)&Al[base1 + k0];
        uint32_t al2 = *(const uint32_t*)&Al[base0 + k0 + 8];
        uint32_t al3 = *(const uint32_t*)&Al[base1 + k0 + 8];
        // kstep 1: real only ci 16..17 -> tg==0 loads, rest zero
        uint32_t bh0s = 0, bh1s = 0, bl0s = 0, bl1s = 0;
        if (tg == 0) {
            bh0s = *(const uint32_t*)&Ah[base0 + 16];
            bh1s = *(const uint32_t*)&Ah[base1 + 16];
            bl0s = *(const uint32_t*)&Al[base0 + 16];
            bl1s = *(const uint32_t*)&Al[base1 + 16];
        }
#pragma unroll
        for (int nt = 0; nt < 5; nt++) {
            const int wrow = (tap * 40 + nt * 8 + g) * 18;
            uint32_t wh0 = *(const uint32_t*)&Wh[wrow + k0];
            uint32_t wh1 = *(const uint32_t*)&Wh[wrow + k0 + 8];
            uint32_t wl0 = *(const uint32_t*)&Wl[wrow + k0];
            uint32_t wl1 = *(const uint32_t*)&Wl[wrow + k0 + 8];
            MMA16816(acc[nt], ah0, ah1, ah2, ah3, wh0, wh1);
            MMA16816(acc[nt], ah0, ah1, ah2, ah3, wl0, wl1);
            MMA16816(acc[nt], al0, al1, al2, al3, wh0, wh1);
            uint32_t wh0s = 0, wl0s = 0;
            if (tg == 0) {
                wh0s = *(const uint32_t*)&Wh[wrow + 16];
                wl0s = *(const uint32_t*)&Wl[wrow + 16];
            }
            MMA16816(acc[nt], bh0s, bh1s, 0u, 0u, wh0s, 0u);
            MMA16816(acc[nt], bh0s, bh1s, 0u, 0u, wl0s, 0u);
            MMA16816(acc[nt], bl0s, bl1s, 0u, 0u, wh0s, 0u);
        }
    }

    // epilogue: transpose through smem (reuse A region), coalesced stores,
    // fused bias + bn2 stats
    __syncthreads();
    float* D = (float*)(sm + AH_OFF);  // [40 co][130 px-stride] = 20800 B
#pragma unroll
    for (int nt = 0; nt < 5; nt++) {
        int co0 = nt * 8 + 2 * tg;
        int p0 = pxb + g;
        D[co0 * 130 + p0] = acc[nt][0];
        D[(co0 + 1) * 130 + p0] = acc[nt][1];
        D[co0 * 130 + p0 + 8] = acc[nt][2];
        D[(co0 + 1) * 130 + p0 + 8] = acc[nt][3];
    }
    __syncthreads();
    for (int co = wid; co < 36; co += 8) {
        float bb = bias[co];
        size_t o = ((size_t)(b * C2 + co) * H + oh) * W + ow0;
        float ts = 0.f, tq = 0.f;
#pragma unroll
        for (int j = 0; j < 4; j++) {
            float v = D[co * 130 + j * 32 + lane] + bb;
            out[o + j * 32 + lane] = v;
            ts += v; tq += v * v;
        }
        ts = warp_red(ts); tq = warp_red(tq);
        if (lane == 0) { atomicAdd(&g_c2_sum[co], ts); atomicAdd(&g_c2_sq[co], tq); }
    }
}

// ---- K5: se2 pooling sums, inline bn2 finalize (reads d_out = raw y2) ---
__global__ __launch_bounds__(256) void stats2_kernel(
    const float* __restrict__ out,
    const float* __restrict__ bn2g, const float* __restrict__ bn2b) {
    __shared__ float sm[8];
    const int bc = blockIdx.x, part = blockIdx.y, tid = threadIdx.x, c = bc % C2;
    const float inv = 1.f / 1048576.f;
    const float m = g_c2_sum[c] * inv;
    const float var = g_c2_sq[c] * inv - m * m;
    const float sc = bn2g[c] * rsqrtf(var + 1e-5f);
    const float sh = bn2b[c] - m * sc;
    const float4* p = (const float4*)(out + (size_t)bc * HW + (size_t)part * 16384);
    float s = 0.f;
    for (int i = tid; i < 4096; i += 256) {
        float4 v = p[i];
        s += lrelu(v.x * sc + sh) + lrelu(v.y * sc + sh)
           + lrelu(v.z * sc + sh) + lrelu(v.w * sc + sh);
    }
    int lane = tid & 31, wid = tid >> 5;
    s = warp_red(s);
    if (lane == 0) sm[wid] = s;
    __syncthreads();
    if (wid == 0) {
        s = (lane < 8) ? sm[lane] : 0.f;
        s = warp_red(s);
        if (lane == 0) atomicAdd(&g_se2_sum[bc], s);
    }
}

// ---- K6: out = lrelu(bn2(out)) * s2 in place, inline bn2 + se2 MLP ------
__global__ __launch_bounds__(256) void finalize_x2_kernel(
    float* __restrict__ out,
    const float* __restrict__ bn2g, const float* __restrict__ bn2b,
    const float* __restrict__ se2w1, const float* __restrict__ se2w2) {
    __shared__ float sh_hh[2];
    const int bc = blockIdx.x, part = blockIdx.y, tid = threadIdx.x;
    const int b = bc / C2, c = bc % C2;
    const float inv = 1.f / 1048576.f;
    const float m = g_c2_sum[c] * inv;
    const float var = g_c2_sq[c] * inv - m * m;
    const float sc = bn2g[c] * rsqrtf(var + 1e-5f);
    const float sh = bn2b[c] - m * sc;
    if (tid < 2) {
        float a = 0.f;
        for (int cc = 0; cc < C2; cc++)
            a += g_se2_sum[b * C2 + cc] * (1.f / 65536.f) * se2w1[tid * C2 + cc];
        sh_hh[tid] = fmaxf(a, 0.f);
    }
    __syncthreads();
    const float s2 = 1.f / (1.f + expf(-(sh_hh[0] * se2w2[c * 2] + sh_hh[1] * se2w2[c * 2 + 1])));
    float4* p = (float4*)(out + (size_t)bc * HW + (size_t)part * 16384);
    for (int i = tid; i < 4096; i += 256) {
        float4 v = p[i];
        v.x = lrelu(v.x * sc + sh) * s2;
        v.y = lrelu(v.y * sc + sh) * s2;
        v.z = lrelu(v.z * sc + sh) * s2;
        v.w = lrelu(v.w * sc + sh) * s2;
        p[i] = v;
    }
}

// ---- K7: head; inline se2 MLP (Haar dwt/idwt collapses to identity) -----
__global__ void final_kernel(const float* __restrict__ fw, const float* __restrict__ fb,
                             const float* __restrict__ se2w1, const float* __restrict__ se2w2,
                             float* __restrict__ out) {
    const int t = threadIdx.x;
    if (t < 32) {
        const int b = t >> 1, k = t & 1;
        const float inv = 1.f / 65536.f;
        float hh0 = 0.f, hh1 = 0.f;
        for (int cc = 0; cc < C2; cc++) {
            float mm = g_se2_sum[b * C2 + cc] * inv;
            hh0 += mm * se2w1[cc];
            hh1 += mm * se2w1[C2 + cc];
        }
        hh0 = fmaxf(hh0, 0.f); hh1 = fmaxf(hh1, 0.f);
        float a = fb[k];
        for (int o = 0; o < C2; o++) {
            float s2 = 1.f / (1.f + expf(-(hh0 * se2w2[o * 2] + hh1 * se2w2[o * 2 + 1])));
            float pool = s2 * g_se2_sum[b * C2 + o] * inv + g_rev_sum[b * C2 + o] * inv;
            a += pool * fw[k * C2 + o];
        }
        out[X2_ELEMS + t] = a;
    }
}

// ---------------- launch ----------------
extern "C" void kernel_launch(void* const* d_in, const int* in_sizes, int n_in,
                              void* d_out, int out_size) {
    const float* x     = (const float*)d_in[0];
    const float* c1w   = (const float*)d_in[1];
    const float* c1b   = (const float*)d_in[2];
    const float* bn1g  = (const float*)d_in[3];
    const float* bn1b  = (const float*)d_in[4];
    const float* se1w1 = (const float*)d_in[5];
    const float* se1w2 = (const float*)d_in[6];
    const float* c2w   = (const float*)d_in[7];
    const float* c2b   = (const float*)d_in[8];
    const float* bn2g  = (const float*)d_in[9];
    const float* bn2b  = (const float*)d_in[10];
    const float* se2w1 = (const float*)d_in[11];
    const float* se2w2 = (const float*)d_in[12];
    const float* rw    = (const float*)d_in[13];
    const float* rb    = (const float*)d_in[14];
    const float* fw    = (const float*)d_in[15];
    const float* fb    = (const float*)d_in[16];
    float* out = (float*)d_out;

    cudaFuncSetAttribute(conv2_mma, cudaFuncAttributeMaxDynamicSharedMemorySize, MMA_SMEM);

    zero_stats<<<1, 576>>>(c2w);                                   // 1
    conv1_kernel<<<dim3(256, 16), 256>>>(x, c1w, c1b);             // 2
    bn1_review_kernel<<<dim3(16, 64), 256>>>(bn1g, bn1b, rw, rb);  // 3
    conv2_mma<<<dim3(2, 256, 16), 256, MMA_SMEM>>>(c2b, bn1g, bn1b, se1w1, se1w2, out); // 4 <- profiled
    stats2_kernel<<<dim3(576, 4), 256>>>(out, bn2g, bn2b);         // 5
    finalize_x2_kernel<<<dim3(576, 4), 256>>>(out, bn2g, bn2b, se2w1, se2w2); // 6
    final_kernel<<<1, 32>>>(fw, fb, se2w1, se2w2, out);            // 7
}